// round 16
// baseline (speedup 1.0000x reference)
#include <cuda_runtime.h>
#include <cuda_fp16.h>
#include <math.h>

#define NLV 50000
#define NPV 150000
#define EV  500000
#define NGV 256

// ---------------- device-global scratch ----------------
__device__ __half g_xl  [NLV*128];
__device__ __half g_xl2 [NLV*128];
__device__ float g_xlsum[NLV*128];
__device__ __half g_prel[NLV*128];
__device__ __half g_xp  [NPV*128];
__device__ __half g_xp2 [NPV*128];
__device__ float g_xpsum[NPV*128];
__device__ __half g_prep[NPV*128];
__device__ __half g_Ah  [(size_t)NLV*512];
__device__ __half g_Bh  [(size_t)NPV*512];
__device__ float g_cvec [512];
__device__ int   g_dst_cnt[NPV];
__device__ int   g_dst_ptr[NPV+1];
__device__ int2  g_dst_edges[EV];   // (edge, partner=src)
__device__ int   g_src_cnt[NLV];
__device__ int   g_src_ptr[NLV+1];
__device__ int2  g_src_edges[EV];   // (edge, partner=dst)
__device__ int   g_scan_tmp[NPV];
__device__ int   g_bsum[512];
__device__ float g_out_w  [NGV*128];
__device__ float g_out_max[NGV*128];

// ---------------- helpers ----------------
__device__ __forceinline__ void atomicMaxFloat(float* addr, float v) {
    if (v >= 0.0f) atomicMax((int*)addr, __float_as_int(v));
    else           atomicMin((unsigned int*)addr, __float_as_uint(v));
}
__device__ __forceinline__ float fast_tanh(float x) {
    float y; asm("tanh.approx.f32 %0, %1;" : "=f"(y) : "f"(x)); return y;
}
__device__ __forceinline__ unsigned packh2(float lo, float hi) {
    __half2 h = __floats2half2_rn(lo, hi);
    return *(unsigned*)&h;
}
__device__ __forceinline__ void mma_f16(float4& d,
        unsigned a0, unsigned a1, unsigned a2, unsigned a3,
        unsigned b0, unsigned b1) {
    asm("mma.sync.aligned.m16n8k16.row.col.f32.f16.f16.f32 "
        "{%0,%1,%2,%3}, {%4,%5,%6,%7}, {%8,%9}, {%0,%1,%2,%3};"
        : "+f"(d.x), "+f"(d.y), "+f"(d.z), "+f"(d.w)
        : "r"(a0), "r"(a1), "r"(a2), "r"(a3), "r"(b0), "r"(b1));
}

// ---------------- node embedding (fp16 out) ----------------
__global__ void k_embed(const float* __restrict__ X, __half* __restrict__ Y,
                        const float* __restrict__ Wn, int M) {
    __shared__ float xs[4][44];
    int r0 = blockIdx.x * 4;
    int tid = threadIdx.x;  // 128
    for (int i = tid; i < 4 * 44; i += 128) {
        int rr = i / 44, kk = i % 44;
        xs[rr][kk] = (r0 + rr < M) ? X[(size_t)(r0 + rr) * 44 + kk] : 0.f;
    }
    __syncthreads();
    int col = tid;
    #pragma unroll
    for (int rr = 0; rr < 4; rr++) {
        if (r0 + rr < M) {
            float s = 0.f;
            #pragma unroll
            for (int kk = 0; kk < 44; kk++) s = fmaf(xs[rr][kk], Wn[kk * 128 + col], s);
            Y[(size_t)(r0 + rr) * 128 + col] = __float2half_rn(s);
        }
    }
}

// ---------------- CSR construction ----------------
__global__ void k_hist(const int* __restrict__ src, const int* __restrict__ dst) {
    int e = blockIdx.x * 256 + threadIdx.x;
    if (e < EV) {
        atomicAdd(&g_dst_cnt[dst[e]], 1);
        atomicAdd(&g_src_cnt[src[e]], 1);
    }
}
__global__ void k_scan1(const int* __restrict__ cnt, int* __restrict__ excl,
                        int* __restrict__ bsum, int n) {
    __shared__ int s[1024];
    int i = blockIdx.x * 1024 + threadIdx.x;
    int v = (i < n) ? cnt[i] : 0;
    s[threadIdx.x] = v;
    __syncthreads();
    for (int off = 1; off < 1024; off <<= 1) {
        int t = 0;
        if ((int)threadIdx.x >= off) t = s[threadIdx.x - off];
        __syncthreads();
        s[threadIdx.x] += t;
        __syncthreads();
    }
    if (i < n) excl[i] = s[threadIdx.x] - v;
    if (threadIdx.x == 1023) bsum[blockIdx.x] = s[1023];
}
__global__ void k_scan2(int* bsum, int nb) {
    __shared__ int s[512];
    int i = threadIdx.x;
    int v = (i < nb) ? bsum[i] : 0;
    s[i] = v;
    __syncthreads();
    for (int off = 1; off < 512; off <<= 1) {
        int t = 0;
        if (i >= off) t = s[i - off];
        __syncthreads();
        s[i] += t;
        __syncthreads();
    }
    if (i < nb) bsum[i] = s[i] - v;
}
__global__ void k_scan3(const int* __restrict__ excl, const int* __restrict__ bsum,
                        int* __restrict__ ptr, int n) {
    int i = blockIdx.x * 1024 + threadIdx.x;
    if (i < n) ptr[i] = excl[i] + bsum[i >> 10];
    if (i == 0) ptr[n] = EV;
}
__global__ void k_fill(const int* __restrict__ src, const int* __restrict__ dst) {
    int e = blockIdx.x * 256 + threadIdx.x;
    if (e < EV) {
        int s = src[e], d = dst[e];
        int p = atomicAdd(&g_dst_cnt[d], 1);
        g_dst_edges[g_dst_ptr[d] + p] = make_int2(e, s);
        int q = atomicAdd(&g_src_cnt[s], 1);
        g_src_edges[g_src_ptr[s] + q] = make_int2(e, d);
    }
}

// ---------------- merged per-layer aggregation (fp16 x, inline rbf) -----------
// lane owns channels {2l, 2l+1, 64+2l, 65+2l}
__global__ __launch_bounds__(256) void k_agg2(
    const __half* __restrict__ xl, const __half* __restrict__ xp,
    const float* __restrict__ ea,
    const float* __restrict__ Wbp, const float* __restrict__ bbp,
    const float* __restrict__ Wbl, const float* __restrict__ bbl,
    __half* __restrict__ prep, __half* __restrict__ prel)
{
    int w = (blockIdx.x * blockDim.x + threadIdx.x) >> 5;
    int lane = threadIdx.x & 31;
    const int* ptr; const int2* eidx; const __half* xsrc;
    const float* Wb_i; const float* bb_i; __half* pre;
    if (w < NPV) {
        ptr = g_dst_ptr; eidx = g_dst_edges; xsrc = xl;
        Wb_i = Wbp; bb_i = bbp; pre = prep;
    } else {
        w -= NPV;
        if (w >= NLV) return;
        ptr = g_src_ptr; eidx = g_src_edges; xsrc = xp;
        Wb_i = Wbl; bb_i = bbl; pre = prel;
    }
    int ch[4] = {2 * lane, 2 * lane + 1, 64 + 2 * lane, 65 + 2 * lane};
    float mu = (5.0f / 7.0f) * (float)lane;
    float wreg[8][4], bias[4], acc[4] = {0.f, 0.f, 0.f, 0.f};
    #pragma unroll
    for (int c = 0; c < 4; c++) {
        bias[c] = bb_i[ch[c]];
        #pragma unroll
        for (int k = 0; k < 8; k++) wreg[k][c] = Wb_i[k * 128 + ch[c]];
    }
    int s = ptr[w], e = ptr[w + 1];
    int p = s;
    for (; p + 2 <= e; p += 2) {
        int2 e0 = eidx[p];
        int2 e1 = eidx[p + 1];
        float d0 = ea[e0.x];
        float d1 = ea[e1.x];
        const __half2* x0 = (const __half2*)(xsrc + (size_t)e0.y * 128);
        const __half2* x1 = (const __half2*)(xsrc + (size_t)e1.y * 128);
        float2 xa0 = __half22float2(x0[lane]);
        float2 xb0 = __half22float2(x0[32 + lane]);
        float2 xa1 = __half22float2(x1[lane]);
        float2 xb1 = __half22float2(x1[32 + lane]);
        float xv0[4] = {xa0.x, xa0.y, xb0.x, xb0.y};
        float xv1[4] = {xa1.x, xa1.y, xb1.x, xb1.y};
        float tt0 = (d0 - mu) * 1.6f, tt1 = (d1 - mu) * 1.6f;
        float rv0 = __expf(-tt0 * tt0), rv1 = __expf(-tt1 * tt1);
        float r0[8], r1[8];
        #pragma unroll
        for (int k = 0; k < 8; k++) {
            r0[k] = __shfl_sync(0xffffffffu, rv0, k);
            r1[k] = __shfl_sync(0xffffffffu, rv1, k);
        }
        #pragma unroll
        for (int c = 0; c < 4; c++) {
            float t0 = bias[c], t1 = bias[c];
            #pragma unroll
            for (int k = 0; k < 8; k++) {
                t0 = fmaf(r0[k], wreg[k][c], t0);
                t1 = fmaf(r1[k], wreg[k][c], t1);
            }
            float sg0 = 1.f / (1.f + __expf(-t0));
            float sg1 = 1.f / (1.f + __expf(-t1));
            acc[c] += (t0 * sg0) * xv0[c] + (t1 * sg1) * xv1[c];
        }
    }
    if (p < e) {
        int2 e0 = eidx[p];
        float d0 = ea[e0.x];
        const __half2* x0 = (const __half2*)(xsrc + (size_t)e0.y * 128);
        float2 xa0 = __half22float2(x0[lane]);
        float2 xb0 = __half22float2(x0[32 + lane]);
        float xv0[4] = {xa0.x, xa0.y, xb0.x, xb0.y};
        float tt0 = (d0 - mu) * 1.6f;
        float rv0 = __expf(-tt0 * tt0);
        float r0[8];
        #pragma unroll
        for (int k = 0; k < 8; k++) r0[k] = __shfl_sync(0xffffffffu, rv0, k);
        #pragma unroll
        for (int c = 0; c < 4; c++) {
            float t0 = bias[c];
            #pragma unroll
            for (int k = 0; k < 8; k++) t0 = fmaf(r0[k], wreg[k][c], t0);
            float sg0 = 1.f / (1.f + __expf(-t0));
            acc[c] += (t0 * sg0) * xv0[c];
        }
    }
    float inv = 1.f / (float)((e - s) > 1 ? (e - s) : 1);
    __half2* po = (__half2*)(pre + (size_t)w * 128);
    po[lane]      = __floats2half2_rn(acc[0] * inv, acc[1] * inv);
    po[32 + lane] = __floats2half2_rn(acc[2] * inv, acc[3] * inv);
}

// ---------------- fp16 mma fused conv GEMM (fp16 A inputs) ----------------
// C[M,128] = lrelu( A0[M,128]@W0 + A1[M,128]@W1 + bias ); sum += C (fp32)
__global__ __launch_bounds__(256, 2) void k_mmac16(
    const __half* __restrict__ A0, const float* __restrict__ W0,
    const __half* __restrict__ A1, const float* __restrict__ W1,
    const float* __restrict__ bias, __half* __restrict__ C,
    float* __restrict__ sum, int M)
{
    __shared__ unsigned AsH[2 * 8 * 136];
    __shared__ unsigned WsH[2 * 8 * 136];
    int tid = threadIdx.x;
    int m0 = blockIdx.y * 128;

    int warp = tid >> 5, lane = tid & 31;
    int g = lane >> 2, t = lane & 3;
    int warp_m = warp >> 1, warp_n = warp & 1;

    int le  = tid >> 1;
    int lk8 = (tid & 1) * 8;
    int kp0 = (tid & 1) * 4;
    int arow = m0 + le;
    int wkp = tid >> 5;
    int wc4 = (tid & 31) * 4;

    float4 facc[2][8];
    #pragma unroll
    for (int mt = 0; mt < 2; mt++)
        #pragma unroll
        for (int nt = 0; nt < 8; nt++) facc[mt][nt] = make_float4(0.f, 0.f, 0.f, 0.f);

    uint4 ua = make_uint4(0, 0, 0, 0);
    float4 pw0, pw1;
    {
        if (arow < M) ua = *(const uint4*)(A0 + (size_t)arow * 128 + lk8);
        const float* pw = W0 + (size_t)(2 * wkp) * 128 + wc4;
        pw0 = *(const float4*)pw; pw1 = *(const float4*)(pw + 128);
    }

    for (int kt = 0; kt < 16; kt++) {
        int buf = (kt & 1) * 1088;
        AsH[buf + (kp0 + 0) * 136 + le] = ua.x;
        AsH[buf + (kp0 + 1) * 136 + le] = ua.y;
        AsH[buf + (kp0 + 2) * 136 + le] = ua.z;
        AsH[buf + (kp0 + 3) * 136 + le] = ua.w;
        WsH[buf + wkp * 136 + wc4 + 0] = packh2(pw0.x, pw1.x);
        WsH[buf + wkp * 136 + wc4 + 1] = packh2(pw0.y, pw1.y);
        WsH[buf + wkp * 136 + wc4 + 2] = packh2(pw0.z, pw1.z);
        WsH[buf + wkp * 136 + wc4 + 3] = packh2(pw0.w, pw1.w);
        if (kt + 1 < 16) {
            int kn = kt + 1;
            const __half* Ab = (kn < 8) ? A0 : A1;
            const float* Wb_ = (kn < 8) ? W0 : W1;
            int kl = (kn & 7) * 16;
            ua = make_uint4(0, 0, 0, 0);
            if (arow < M) ua = *(const uint4*)(Ab + (size_t)arow * 128 + kl + lk8);
            const float* pw = Wb_ + (size_t)(kl + 2 * wkp) * 128 + wc4;
            pw0 = *(const float4*)pw; pw1 = *(const float4*)(pw + 128);
        }
        __syncthreads();
        unsigned af[2][4];
        #pragma unroll
        for (int mt = 0; mt < 2; mt++) {
            int rowb = warp_m * 32 + mt * 16;
            af[mt][0] = AsH[buf + t * 136 + rowb + g];
            af[mt][1] = AsH[buf + t * 136 + rowb + g + 8];
            af[mt][2] = AsH[buf + (t + 4) * 136 + rowb + g];
            af[mt][3] = AsH[buf + (t + 4) * 136 + rowb + g + 8];
        }
        #pragma unroll
        for (int nt = 0; nt < 8; nt++) {
            int colb = warp_n * 64 + nt * 8;
            unsigned bf0 = WsH[buf + t * 136 + colb + g];
            unsigned bf1 = WsH[buf + (t + 4) * 136 + colb + g];
            mma_f16(facc[0][nt], af[0][0], af[0][1], af[0][2], af[0][3], bf0, bf1);
            mma_f16(facc[1][nt], af[1][0], af[1][1], af[1][2], af[1][3], bf0, bf1);
        }
    }
    #pragma unroll
    for (int mt = 0; mt < 2; mt++) {
        int rowb = m0 + warp_m * 32 + mt * 16;
        #pragma unroll
        for (int nt = 0; nt < 8; nt++) {
            int col = warp_n * 64 + nt * 8 + 2 * t;
            float ba = bias[col], bb_ = bias[col + 1];
            int r0 = rowb + g, r1 = rowb + g + 8;
            float vx = facc[mt][nt].x + ba, vy = facc[mt][nt].y + bb_;
            float vz = facc[mt][nt].z + ba, vw = facc[mt][nt].w + bb_;
            vx = (vx >= 0.f) ? vx : 0.01f * vx;
            vy = (vy >= 0.f) ? vy : 0.01f * vy;
            vz = (vz >= 0.f) ? vz : 0.01f * vz;
            vw = (vw >= 0.f) ? vw : 0.01f * vw;
            if (r0 < M) {
                *(__half2*)(C + (size_t)r0 * 128 + col) = __floats2half2_rn(vx, vy);
                float2 s = *(float2*)(sum + (size_t)r0 * 128 + col);
                s.x += vx; s.y += vy;
                *(float2*)(sum + (size_t)r0 * 128 + col) = s;
            }
            if (r1 < M) {
                *(__half2*)(C + (size_t)r1 * 128 + col) = __floats2half2_rn(vz, vw);
                float2 s = *(float2*)(sum + (size_t)r1 * 128 + col);
                s.x += vz; s.y += vw;
                *(float2*)(sum + (size_t)r1 * 128 + col) = s;
            }
        }
    }
}

// ---------------- fp16 mma factor GEMM: Ch[M,N] = A[M,128]@W[128,N] + bias -----
__global__ __launch_bounds__(256, 2) void k_mma16(
    const float* __restrict__ A, const float* __restrict__ W,
    const float* __restrict__ bias, __half* __restrict__ C,
    int M, int N)
{
    __shared__ unsigned AsH[2 * 8 * 136];
    __shared__ unsigned WsH[2 * 8 * 136];
    int tid = threadIdx.x;
    int m0 = blockIdx.y * 128;
    int n0 = blockIdx.x * 128;

    int warp = tid >> 5, lane = tid & 31;
    int g = lane >> 2, t = lane & 3;
    int warp_m = warp >> 1, warp_n = warp & 1;

    int le  = tid >> 1;
    int lk8 = (tid & 1) * 8;
    int kp0 = (tid & 1) * 4;
    int arow = m0 + le;
    int wkp = tid >> 5;
    int wc4 = (tid & 31) * 4;

    float4 facc[2][8];
    #pragma unroll
    for (int mt = 0; mt < 2; mt++)
        #pragma unroll
        for (int nt = 0; nt < 8; nt++) facc[mt][nt] = make_float4(0.f, 0.f, 0.f, 0.f);

    float4 pa0, pa1, pw0, pw1;
    {
        pa0 = make_float4(0.f,0.f,0.f,0.f); pa1 = pa0;
        if (arow < M) {
            const float* p = A + (size_t)arow * 128 + lk8;
            pa0 = *(const float4*)p; pa1 = *(const float4*)(p + 4);
        }
        const float* pw = W + (size_t)(2 * wkp) * N + n0 + wc4;
        pw0 = *(const float4*)pw; pw1 = *(const float4*)(pw + N);
    }

    for (int kt = 0; kt < 8; kt++) {
        int buf = (kt & 1) * 1088;
        int k = kt * 16;
        AsH[buf + (kp0 + 0) * 136 + le] = packh2(pa0.x, pa0.y);
        AsH[buf + (kp0 + 1) * 136 + le] = packh2(pa0.z, pa0.w);
        AsH[buf + (kp0 + 2) * 136 + le] = packh2(pa1.x, pa1.y);
        AsH[buf + (kp0 + 3) * 136 + le] = packh2(pa1.z, pa1.w);
        WsH[buf + wkp * 136 + wc4 + 0] = packh2(pw0.x, pw1.x);
        WsH[buf + wkp * 136 + wc4 + 1] = packh2(pw0.y, pw1.y);
        WsH[buf + wkp * 136 + wc4 + 2] = packh2(pw0.z, pw1.z);
        WsH[buf + wkp * 136 + wc4 + 3] = packh2(pw0.w, pw1.w);
        if (kt + 1 < 8) {
            int kn = k + 16;
            pa0 = make_float4(0.f,0.f,0.f,0.f); pa1 = pa0;
            if (arow < M) {
                const float* p = A + (size_t)arow * 128 + kn + lk8;
                pa0 = *(const float4*)p; pa1 = *(const float4*)(p + 4);
            }
            const float* pw = W + (size_t)(kn + 2 * wkp) * N + n0 + wc4;
            pw0 = *(const float4*)pw; pw1 = *(const float4*)(pw + N);
        }
        __syncthreads();
        unsigned af[2][4];
        #pragma unroll
        for (int mt = 0; mt < 2; mt++) {
            int rowb = warp_m * 32 + mt * 16;
            af[mt][0] = AsH[buf + t * 136 + rowb + g];
            af[mt][1] = AsH[buf + t * 136 + rowb + g + 8];
            af[mt][2] = AsH[buf + (t + 4) * 136 + rowb + g];
            af[mt][3] = AsH[buf + (t + 4) * 136 + rowb + g + 8];
        }
        #pragma unroll
        for (int nt = 0; nt < 8; nt++) {
            int colb = warp_n * 64 + nt * 8;
            unsigned bf0 = WsH[buf + t * 136 + colb + g];
            unsigned bf1 = WsH[buf + (t + 4) * 136 + colb + g];
            mma_f16(facc[0][nt], af[0][0], af[0][1], af[0][2], af[0][3], bf0, bf1);
            mma_f16(facc[1][nt], af[1][0], af[1][1], af[1][2], af[1][3], bf0, bf1);
        }
    }
    #pragma unroll
    for (int mt = 0; mt < 2; mt++) {
        int rowb = m0 + warp_m * 32 + mt * 16;
        #pragma unroll
        for (int nt = 0; nt < 8; nt++) {
            int col = n0 + warp_n * 64 + nt * 8 + 2 * t;
            float ba = 0.f, bb_ = 0.f;
            if (bias) { ba = bias[col]; bb_ = bias[col + 1]; }
            int r0 = rowb + g, r1 = rowb + g + 8;
            if (r0 < M)
                *(__half2*)(C + (size_t)r0 * N + col) =
                    __floats2half2_rn(facc[mt][nt].x + ba, facc[mt][nt].y + bb_);
            if (r1 < M)
                *(__half2*)(C + (size_t)r1 * N + col) =
                    __floats2half2_rn(facc[mt][nt].z + ba, facc[mt][nt].w + bb_);
        }
    }
}

// ---------------- cvec ----------------
__global__ void k_cvec(const float* __restrict__ W_el, const float* __restrict__ W1) {
    int j = blockIdx.x * 256 + threadIdx.x;
    if (j < 512) {
        float s = 0.f;
        #pragma unroll
        for (int k = 0; k < 8; k++) s = fmaf(W_el[k], W1[(size_t)(256 + k) * 512 + j], s);
        g_cvec[j] = s;
    }
}

__global__ void k_init_out() {
    int i = blockIdx.x * 256 + threadIdx.x;
    if (i < NGV * 128) { g_out_w[i] = 0.f; g_out_max[i] = -INFINITY; }
}

// ---------------- fused edge MLP + per-graph reduction: 128-edge tiles ------------
#define EDGE_SMEM_FLOATS 22272
__global__ __launch_bounds__(256, 2) void k_edge(
    const __half* __restrict__ Al, const __half* __restrict__ Bp,
    const float* __restrict__ W2, const float* __restrict__ b2,
    const float* __restrict__ Wm, const float* __restrict__ bm,
    const int* __restrict__ src,
    const float* __restrict__ ea, const int* __restrict__ lbatch)
{
    extern __shared__ float dynsm[];
    unsigned* AsH = (unsigned*)dynsm;
    unsigned* WsH = (unsigned*)(dynsm + 2176);
    float* smm  = dynsm + 4352;
    float* cs   = dynsm + 21248;
    float* se_d = dynsm + 21760;
    int*   se_a = (int*)(dynsm + 21888);
    int*   se_b = (int*)(dynsm + 22016);
    int*   se_g = (int*)(dynsm + 22144);

    int tid = threadIdx.x;
    int t0 = blockIdx.x * 128;
    if (tid < 128) {
        int slot = t0 + tid;
        if (slot < EV) {
            int2 ei = g_src_edges[slot];
            int e = ei.x;
            int s = src[e];
            se_a[tid] = s; se_b[tid] = ei.y;
            se_d[tid] = ea[e];
            se_g[tid] = lbatch[s];
        } else { se_a[tid] = 0; se_b[tid] = 0; se_d[tid] = 0.f; se_g[tid] = -1; }
    }
    for (int i = tid; i < 512; i += 256) cs[i] = g_cvec[i];
    __syncthreads();

    int warp = tid >> 5, lane = tid & 31;
    int g = lane >> 2, t = lane & 3;
    int warp_m = warp >> 1, warp_n = warp & 1;

    int le  = tid >> 1;
    int lk8 = (tid & 1) * 8;
    int kp0 = (tid & 1) * 4;
    const __half* arow = Al + (size_t)se_a[le] * 512;
    const __half* brow = Bp + (size_t)se_b[le] * 512;
    float dv = se_d[le];
    int wkp = tid >> 5;
    int wc4 = (tid & 31) * 4;

    // ---- GEMM 1 (fp16 mma): m = relu(A[src]+B[dst]+d*cvec) @ W2 ----
    float4 facc[2][8];
    #pragma unroll
    for (int mt = 0; mt < 2; mt++)
        #pragma unroll
        for (int nt = 0; nt < 8; nt++) facc[mt][nt] = make_float4(0.f, 0.f, 0.f, 0.f);

    uint4 pa, pb;
    float4 pw0, pw1;
    {
        pa = *(const uint4*)(arow + lk8);
        pb = *(const uint4*)(brow + lk8);
        const float* pw = W2 + (size_t)(2 * wkp) * 128 + wc4;
        pw0 = *(const float4*)pw; pw1 = *(const float4*)(pw + 128);
    }

    for (int kt = 0; kt < 32; kt++) {
        int buf = (kt & 1) * 1088;
        int k = kt * 16;
        float4 c0 = *(const float4*)(cs + k + lk8), c1 = *(const float4*)(cs + k + lk8 + 4);
        const __half2* a2 = (const __half2*)&pa;
        const __half2* b2v = (const __half2*)&pb;
        float2 fa0 = __half22float2(a2[0]), fb0 = __half22float2(b2v[0]);
        float2 fa1 = __half22float2(a2[1]), fb1 = __half22float2(b2v[1]);
        float2 fa2 = __half22float2(a2[2]), fb2 = __half22float2(b2v[2]);
        float2 fa3 = __half22float2(a2[3]), fb3 = __half22float2(b2v[3]);
        float h0 = fmaxf(fa0.x + fb0.x + dv * c0.x, 0.f);
        float h1 = fmaxf(fa0.y + fb0.y + dv * c0.y, 0.f);
        float h2 = fmaxf(fa1.x + fb1.x + dv * c0.z, 0.f);
        float h3 = fmaxf(fa1.y + fb1.y + dv * c0.w, 0.f);
        float h4 = fmaxf(fa2.x + fb2.x + dv * c1.x, 0.f);
        float h5 = fmaxf(fa2.y + fb2.y + dv * c1.y, 0.f);
        float h6 = fmaxf(fa3.x + fb3.x + dv * c1.z, 0.f);
        float h7 = fmaxf(fa3.y + fb3.y + dv * c1.w, 0.f);
        AsH[buf + (kp0 + 0) * 136 + le] = packh2(h0, h1);
        AsH[buf + (kp0 + 1) * 136 + le] = packh2(h2, h3);
        AsH[buf + (kp0 + 2) * 136 + le] = packh2(h4, h5);
        AsH[buf + (kp0 + 3) * 136 + le] = packh2(h6, h7);
        WsH[buf + wkp * 136 + wc4 + 0] = packh2(pw0.x, pw1.x);
        WsH[buf + wkp * 136 + wc4 + 1] = packh2(pw0.y, pw1.y);
        WsH[buf + wkp * 136 + wc4 + 2] = packh2(pw0.z, pw1.z);
        WsH[buf + wkp * 136 + wc4 + 3] = packh2(pw0.w, pw1.w);
        if (kt + 1 < 32) {
            int kn = k + 16;
            pa = *(const uint4*)(arow + kn + lk8);
            pb = *(const uint4*)(brow + kn + lk8);
            const float* pw = W2 + (size_t)(kn + 2 * wkp) * 128 + wc4;
            pw0 = *(const float4*)pw; pw1 = *(const float4*)(pw + 128);
        }
        __syncthreads();
        unsigned af[2][4];
        #pragma unroll
        for (int mt = 0; mt < 2; mt++) {
            int rowb = warp_m * 32 + mt * 16;
            af[mt][0] = AsH[buf + t * 136 + rowb + g];
            af[mt][1] = AsH[buf + t * 136 + rowb + g + 8];
            af[mt][2] = AsH[buf + (t + 4) * 136 + rowb + g];
            af[mt][3] = AsH[buf + (t + 4) * 136 + rowb + g + 8];
        }
        #pragma unroll
        for (int nt = 0; nt < 8; nt++) {
            int colb = warp_n * 64 + nt * 8;
            unsigned bf0 = WsH[buf + t * 136 + colb + g];
            unsigned bf1 = WsH[buf + (t + 4) * 136 + colb + g];
            mma_f16(facc[0][nt], af[0][0], af[0][1], af[0][2], af[0][3], bf0, bf1);
            mma_f16(facc[1][nt], af[1][0], af[1][1], af[1][2], af[1][3], bf0, bf1);
        }
    }
    __syncthreads();

    // m = facc + b2 -> smm (fragment-layout stores, fp32)
    #pragma unroll
    for (int mt = 0; mt < 2; mt++) {
        int rowb = warp_m * 32 + mt * 16;
        #pragma unroll
        for (int nt = 0; nt < 8; nt++) {
            int cc = warp_n * 64 + nt * 8 + 2 * t;
            float ba = b2[cc], bb_ = b2[cc + 1];
            *(float2*)(smm + (rowb + g) * 132 + cc) =
                make_float2(facc[mt][nt].x + ba, facc[mt][nt].y + bb_);
            *(float2*)(smm + (rowb + g + 8) * 132 + cc) =
                make_float2(facc[mt][nt].z + ba, facc[mt][nt].w + bb_);
        }
    }
    __syncthreads();

    // ---- GEMM 2 (fp16 mma): u = m @ Wm ; w = tanh(u + bm) ----
    float4 facc2[2][8];
    #pragma unroll
    for (int mt = 0; mt < 2; mt++)
        #pragma unroll
        for (int nt = 0; nt < 8; nt++) facc2[mt][nt] = make_float4(0.f, 0.f, 0.f, 0.f);

    {
        const float* pw = Wm + (size_t)(2 * wkp) * 128 + wc4;
        pw0 = *(const float4*)pw; pw1 = *(const float4*)(pw + 128);
    }
    for (int kt = 0; kt < 8; kt++) {
        int buf = (kt & 1) * 1088;
        int k = kt * 16;
        WsH[buf + wkp * 136 + wc4 + 0] = packh2(pw0.x, pw1.x);
        WsH[buf + wkp * 136 + wc4 + 1] = packh2(pw0.y, pw1.y);
        WsH[buf + wkp * 136 + wc4 + 2] = packh2(pw0.z, pw1.z);
        WsH[buf + wkp * 136 + wc4 + 3] = packh2(pw0.w, pw1.w);
        if (kt + 1 < 8) {
            const float* pw = Wm + (size_t)(k + 16 + 2 * wkp) * 128 + wc4;
            pw0 = *(const float4*)pw; pw1 = *(const float4*)(pw + 128);
        }
        __syncthreads();
        unsigned af[2][4];
        #pragma unroll
        for (int mt = 0; mt < 2; mt++) {
            int rowb = warp_m * 32 + mt * 16;
            const float* r0p = smm + (rowb + g) * 132 + k;
            const float* r1p = smm + (rowb + g + 8) * 132 + k;
            af[mt][0] = packh2(r0p[2 * t], r0p[2 * t + 1]);
            af[mt][1] = packh2(r1p[2 * t], r1p[2 * t + 1]);
            af[mt][2] = packh2(r0p[2 * t + 8], r0p[2 * t + 9]);
            af[mt][3] = packh2(r1p[2 * t + 8], r1p[2 * t + 9]);
        }
        #pragma unroll
        for (int nt = 0; nt < 8; nt++) {
            int colb = warp_n * 64 + nt * 8;
            unsigned bf0 = WsH[buf + t * 136 + colb + g];
            unsigned bf1 = WsH[buf + (t + 4) * 136 + colb + g];
            mma_f16(facc2[0][nt], af[0][0], af[0][1], af[0][2], af[0][3], bf0, bf1);
            mma_f16(facc2[1][nt], af[1][0], af[1][1], af[1][2], af[1][3], bf0, bf1);
        }
    }

    // ---- per-graph reduction (fragment layout) ----
    {
        int row_block = warp_m * 32;
        bool uniform = (se_g[row_block] == se_g[row_block + 31]) && (se_g[row_block] >= 0);
        if (uniform) {
            int gg = se_g[row_block];
            #pragma unroll
            for (int nt = 0; nt < 8; nt++) {
                int cc = warp_n * 64 + nt * 8 + 2 * t;
                float b0 = bm[cc], b1 = bm[cc + 1];
                float ps0 = 0.f, ps1 = 0.f, mx0 = -INFINITY, mx1 = -INFINITY;
                #pragma unroll
                for (int mt = 0; mt < 2; mt++) {
                    int r0 = warp_m * 32 + mt * 16 + g, r1 = r0 + 8;
                    float m00 = smm[r0 * 132 + cc], m01 = smm[r0 * 132 + cc + 1];
                    float m10 = smm[r1 * 132 + cc], m11 = smm[r1 * 132 + cc + 1];
                    ps0 += fast_tanh(facc2[mt][nt].x + b0) * m00
                         + fast_tanh(facc2[mt][nt].z + b0) * m10;
                    ps1 += fast_tanh(facc2[mt][nt].y + b1) * m01
                         + fast_tanh(facc2[mt][nt].w + b1) * m11;
                    mx0 = fmaxf(mx0, fmaxf(m00, m10));
                    mx1 = fmaxf(mx1, fmaxf(m01, m11));
                }
                #pragma unroll
                for (int off = 4; off < 32; off <<= 1) {
                    ps0 += __shfl_xor_sync(0xffffffffu, ps0, off);
                    ps1 += __shfl_xor_sync(0xffffffffu, ps1, off);
                    mx0 = fmaxf(mx0, __shfl_xor_sync(0xffffffffu, mx0, off));
                    mx1 = fmaxf(mx1, __shfl_xor_sync(0xffffffffu, mx1, off));
                }
                if (g == 0) {
                    atomicAdd(&g_out_w[gg * 128 + cc], ps0);
                    atomicAdd(&g_out_w[gg * 128 + cc + 1], ps1);
                    atomicMaxFloat(&g_out_max[gg * 128 + cc], mx0);
                    atomicMaxFloat(&g_out_max[gg * 128 + cc + 1], mx1);
                }
            }
        } else {
            #pragma unroll
            for (int nt = 0; nt < 8; nt++) {
                int cc = warp_n * 64 + nt * 8 + 2 * t;
                float b0 = bm[cc], b1 = bm[cc + 1];
                #pragma unroll
                for (int mt = 0; mt < 2; mt++) {
                    int r0 = warp_m * 32 + mt * 16 + g, r1 = r0 + 8;
                    int g0 = se_g[r0], g1 = se_g[r1];
                    if (g0 >= 0) {
                        float m00 = smm[r0 * 132 + cc], m01 = smm[r0 * 132 + cc + 1];
                        atomicAdd(&g_out_w[g0 * 128 + cc],
                                  fast_tanh(facc2[mt][nt].x + b0) * m00);
                        atomicAdd(&g_out_w[g0 * 128 + cc + 1],
                                  fast_tanh(facc2[mt][nt].y + b1) * m01);
                        atomicMaxFloat(&g_out_max[g0 * 128 + cc], m00);
                        atomicMaxFloat(&g_out_max[g0 * 128 + cc + 1], m01);
                    }
                    if (g1 >= 0) {
                        float m10 = smm[r1 * 132 + cc], m11 = smm[r1 * 132 + cc + 1];
                        atomicAdd(&g_out_w[g1 * 128 + cc],
                                  fast_tanh(facc2[mt][nt].z + b0) * m10);
                        atomicAdd(&g_out_w[g1 * 128 + cc + 1],
                                  fast_tanh(facc2[mt][nt].w + b1) * m11);
                        atomicMaxFloat(&g_out_max[g1 * 128 + cc], m10);
                        atomicMaxFloat(&g_out_max[g1 * 128 + cc + 1], m11);
                    }
                }
            }
        }
    }
}

__global__ void k_final(float* __restrict__ out) {
    int i = blockIdx.x * 256 + threadIdx.x;
    if (i < NGV * 256) {
        int g = i >> 8, j = i & 255;
        float v;
        if (j < 128) v = g_out_w[g * 128 + j];
        else {
            v = g_out_max[g * 128 + j - 128];
            if (!isfinite(v)) v = 0.f;
        }
        out[i] = v;
    }
}

// ---------------- host orchestration ----------------
#define SYM(p, s) do { void* _t = nullptr; cudaGetSymbolAddress(&_t, s); p = (decltype(p))_t; } while (0)

extern "C" void kernel_launch(void* const* d_in, const int* in_sizes, int n_in,
                              void* d_out, int out_size) {
    const float* x_l    = (const float*)d_in[0];
    const float* x_p    = (const float*)d_in[1];
    const float* ea     = (const float*)d_in[2];
    const int*   esrc   = (const int*)  d_in[3];
    const int*   edst   = (const int*)  d_in[4];
    const int*   lbatch = (const int*)  d_in[5];
    const float* W_node = (const float*)d_in[6];
    const float* W_el   = (const float*)d_in[7];
    const float* Wb     = (const float*)d_in[8];
    const float* bb     = (const float*)d_in[9];
    const float* Wn     = (const float*)d_in[10];
    const float* Ws_    = (const float*)d_in[11];
    const float* bconv  = (const float*)d_in[12];
    const float* W1     = (const float*)d_in[13];
    const float* b1     = (const float*)d_in[14];
    const float* W2     = (const float*)d_in[15];
    const float* b2     = (const float*)d_in[16];
    const float* Wm     = (const float*)d_in[17];
    const float* bm     = (const float*)d_in[18];

    __half *xl, *xl2, *prel, *xp, *xp2, *prep, *Ah, *Bh;
    float *xlsum, *xpsum;
    int *dcnt, *dptr, *scnt, *sptr, *stmp, *bsum;
    SYM(xl, g_xl); SYM(xl2, g_xl2); SYM(xlsum, g_xlsum); SYM(prel, g_prel);
    SYM(xp, g_xp); SYM(xp2, g_xp2); SYM(xpsum, g_xpsum); SYM(prep, g_prep);
    SYM(Ah, g_Ah); SYM(Bh, g_Bh);
    SYM(dcnt, g_dst_cnt); SYM(dptr, g_dst_ptr);
    SYM(scnt, g_src_cnt); SYM(sptr, g_src_ptr);
    SYM(stmp, g_scan_tmp); SYM(bsum, g_bsum);

    cudaFuncSetAttribute(k_edge, cudaFuncAttributeMaxDynamicSharedMemorySize,
                         EDGE_SMEM_FLOATS * (int)sizeof(float));

    // node embedding (fp16 out)
    k_embed<<<(NLV + 3) / 4, 128>>>(x_l, xl, W_node, NLV);
    k_embed<<<(NPV + 3) / 4, 128>>>(x_p, xp, W_node, NPV);

    // cvec
    k_cvec<<<2, 256>>>(W_el, W1);

    // CSR (dst and src)
    cudaMemsetAsync(dcnt, 0, NPV * sizeof(int));
    cudaMemsetAsync(scnt, 0, NLV * sizeof(int));
    k_hist<<<(EV + 255) / 256, 256>>>(esrc, edst);
    int nbp = (NPV + 1023) / 1024, nbl = (NLV + 1023) / 1024;
    k_scan1<<<nbp, 1024>>>(dcnt, stmp, bsum, NPV);
    k_scan2<<<1, 512>>>(bsum, nbp);
    k_scan3<<<nbp, 1024>>>(stmp, bsum, dptr, NPV);
    k_scan1<<<nbl, 1024>>>(scnt, stmp, bsum, NLV);
    k_scan2<<<1, 512>>>(bsum, nbl);
    k_scan3<<<nbl, 1024>>>(stmp, bsum, sptr, NLV);
    cudaMemsetAsync(dcnt, 0, NPV * sizeof(int));
    cudaMemsetAsync(scnt, 0, NLV * sizeof(int));
    k_fill<<<(EV + 255) / 256, 256>>>(esrc, edst);

    // running sums
    cudaMemsetAsync(xlsum, 0, (size_t)NLV * 128 * sizeof(float));
    cudaMemsetAsync(xpsum, 0, (size_t)NPV * 128 * sizeof(float));

    // 3 hetero layers (fp16 storage + fp16 mma)
    __half *cxl = xl, *cxp = xp, *nxl = xl2, *nxp = xp2;
    for (int l = 0; l < 3; l++) {
        int ilp = 2 * l, ipl = 2 * l + 1;
        k_agg2<<<((NPV + NLV) * 32 + 255) / 256, 256>>>(cxl, cxp, ea,
                Wb + ilp * 1024, bb + ilp * 128,
                Wb + ipl * 1024, bb + ipl * 128, prep, prel);
        k_mmac16<<<dim3(1, (NPV + 127) / 128), 256>>>(cxp, Ws_ + (size_t)ilp * 16384,
                prep, Wn + (size_t)ilp * 16384, bconv + ilp * 128,
                nxp, xpsum, NPV);
        k_mmac16<<<dim3(1, (NLV + 127) / 128), 256>>>(cxl, Ws_ + (size_t)ipl * 16384,
                prel, Wn + (size_t)ipl * 16384, bconv + ipl * 128,
                nxl, xlsum, NLV);
        __half* t;
        t = cxl; cxl = nxl; nxl = t;
        t = cxp; cxp = nxp; nxp = t;
    }

    // edge readout factorization (fp16 mma, fp16 output)
    k_mma16<<<dim3(4, (NLV + 127) / 128), 256>>>(xlsum, W1, b1, Ah, NLV, 512);
    k_mma16<<<dim3(4, (NPV + 127) / 128), 256>>>(xpsum, W1 + (size_t)128 * 512,
                                                 nullptr, Bh, NPV, 512);

    k_init_out<<<(NGV * 128 + 255) / 256, 256>>>();
    k_edge<<<(EV + 127) / 128, 256, EDGE_SMEM_FLOATS * (int)sizeof(float)>>>(
            Ah, Bh, W2, b2, Wm, bm, esrc, ea, lbatch);
    k_final<<<(NGV * 256 + 255) / 256, 256>>>((float*)d_out);
}

// round 17
// speedup vs baseline: 1.0541x; 1.0541x over previous
#include <cuda_runtime.h>
#include <cuda_fp16.h>
#include <math.h>

#define NLV 50000
#define NPV 150000
#define EV  500000
#define NGV 256

// ---------------- device-global scratch ----------------
__device__ __half g_xl  [NLV*128];
__device__ __half g_xl2 [NLV*128];
__device__ float g_xlsum[NLV*128];
__device__ __half g_prel[NLV*128];
__device__ __half g_xp  [NPV*128];
__device__ __half g_xp2 [NPV*128];
__device__ float g_xpsum[NPV*128];
__device__ __half g_prep[NPV*128];
__device__ __half g_Ah  [(size_t)NLV*512];
__device__ __half g_Bh  [(size_t)NPV*512];
__device__ float g_cvec [512];
__device__ int   g_dst_cnt[NPV];
__device__ int   g_dst_ptr[NPV+1];
__device__ int2  g_dst_edges[EV];   // (partner=src, d_bits)
__device__ int   g_src_cnt[NLV];
__device__ int   g_src_ptr[NLV+1];
__device__ int2  g_src_edges[EV];   // (partner=dst, d_bits)
__device__ int4  g_src_rec [EV];    // (src, dst, d_bits, batch)
__device__ int   g_scan_tmp[NPV];
__device__ int   g_bsum[512];
__device__ float g_out_w  [NGV*128];
__device__ float g_out_max[NGV*128];

// ---------------- helpers ----------------
__device__ __forceinline__ void atomicMaxFloat(float* addr, float v) {
    if (v >= 0.0f) atomicMax((int*)addr, __float_as_int(v));
    else           atomicMin((unsigned int*)addr, __float_as_uint(v));
}
__device__ __forceinline__ float fast_tanh(float x) {
    float y; asm("tanh.approx.f32 %0, %1;" : "=f"(y) : "f"(x)); return y;
}
__device__ __forceinline__ unsigned packh2(float lo, float hi) {
    __half2 h = __floats2half2_rn(lo, hi);
    return *(unsigned*)&h;
}
__device__ __forceinline__ void mma_f16(float4& d,
        unsigned a0, unsigned a1, unsigned a2, unsigned a3,
        unsigned b0, unsigned b1) {
    asm("mma.sync.aligned.m16n8k16.row.col.f32.f16.f16.f32 "
        "{%0,%1,%2,%3}, {%4,%5,%6,%7}, {%8,%9}, {%0,%1,%2,%3};"
        : "+f"(d.x), "+f"(d.y), "+f"(d.z), "+f"(d.w)
        : "r"(a0), "r"(a1), "r"(a2), "r"(a3), "r"(b0), "r"(b1));
}

// ---------------- node embedding (fp16 out) ----------------
__global__ void k_embed(const float* __restrict__ X, __half* __restrict__ Y,
                        const float* __restrict__ Wn, int M) {
    __shared__ float xs[4][44];
    int r0 = blockIdx.x * 4;
    int tid = threadIdx.x;  // 128
    for (int i = tid; i < 4 * 44; i += 128) {
        int rr = i / 44, kk = i % 44;
        xs[rr][kk] = (r0 + rr < M) ? X[(size_t)(r0 + rr) * 44 + kk] : 0.f;
    }
    __syncthreads();
    int col = tid;
    #pragma unroll
    for (int rr = 0; rr < 4; rr++) {
        if (r0 + rr < M) {
            float s = 0.f;
            #pragma unroll
            for (int kk = 0; kk < 44; kk++) s = fmaf(xs[rr][kk], Wn[kk * 128 + col], s);
            Y[(size_t)(r0 + rr) * 128 + col] = __float2half_rn(s);
        }
    }
}

// ---------------- CSR construction ----------------
__global__ void k_hist(const int* __restrict__ src, const int* __restrict__ dst) {
    int e = blockIdx.x * 256 + threadIdx.x;
    if (e < EV) {
        atomicAdd(&g_dst_cnt[dst[e]], 1);
        atomicAdd(&g_src_cnt[src[e]], 1);
    }
}
__global__ void k_scan1(const int* __restrict__ cnt, int* __restrict__ excl,
                        int* __restrict__ bsum, int n) {
    __shared__ int s[1024];
    int i = blockIdx.x * 1024 + threadIdx.x;
    int v = (i < n) ? cnt[i] : 0;
    s[threadIdx.x] = v;
    __syncthreads();
    for (int off = 1; off < 1024; off <<= 1) {
        int t = 0;
        if ((int)threadIdx.x >= off) t = s[threadIdx.x - off];
        __syncthreads();
        s[threadIdx.x] += t;
        __syncthreads();
    }
    if (i < n) excl[i] = s[threadIdx.x] - v;
    if (threadIdx.x == 1023) bsum[blockIdx.x] = s[1023];
}
__global__ void k_scan2(int* bsum, int nb) {
    __shared__ int s[512];
    int i = threadIdx.x;
    int v = (i < nb) ? bsum[i] : 0;
    s[i] = v;
    __syncthreads();
    for (int off = 1; off < 512; off <<= 1) {
        int t = 0;
        if (i >= off) t = s[i - off];
        __syncthreads();
        s[i] += t;
        __syncthreads();
    }
    if (i < nb) bsum[i] = s[i] - v;
}
__global__ void k_scan3(const int* __restrict__ excl, const int* __restrict__ bsum,
                        int* __restrict__ ptr, int n) {
    int i = blockIdx.x * 1024 + threadIdx.x;
    if (i < n) ptr[i] = excl[i] + bsum[i >> 10];
    if (i == 0) ptr[n] = EV;
}
__global__ void k_fill(const int* __restrict__ src, const int* __restrict__ dst,
                       const float* __restrict__ ea, const int* __restrict__ lbatch) {
    int e = blockIdx.x * 256 + threadIdx.x;
    if (e < EV) {
        int s = src[e], d = dst[e];
        int dbits = __float_as_int(ea[e]);
        int p = atomicAdd(&g_dst_cnt[d], 1);
        g_dst_edges[g_dst_ptr[d] + p] = make_int2(s, dbits);
        int q = atomicAdd(&g_src_cnt[s], 1);
        int slot = g_src_ptr[s] + q;
        g_src_edges[slot] = make_int2(d, dbits);
        g_src_rec[slot] = make_int4(s, d, dbits, lbatch[s]);
    }
}

// ---------------- merged per-layer aggregation (d embedded in CSR) ------------
// lane owns channels {2l, 2l+1, 64+2l, 65+2l}
__global__ __launch_bounds__(256) void k_agg2(
    const __half* __restrict__ xl, const __half* __restrict__ xp,
    const float* __restrict__ Wbp, const float* __restrict__ bbp,
    const float* __restrict__ Wbl, const float* __restrict__ bbl,
    __half* __restrict__ prep, __half* __restrict__ prel)
{
    int w = (blockIdx.x * blockDim.x + threadIdx.x) >> 5;
    int lane = threadIdx.x & 31;
    const int* ptr; const int2* eidx; const __half* xsrc;
    const float* Wb_i; const float* bb_i; __half* pre;
    if (w < NPV) {
        ptr = g_dst_ptr; eidx = g_dst_edges; xsrc = xl;
        Wb_i = Wbp; bb_i = bbp; pre = prep;
    } else {
        w -= NPV;
        if (w >= NLV) return;
        ptr = g_src_ptr; eidx = g_src_edges; xsrc = xp;
        Wb_i = Wbl; bb_i = bbl; pre = prel;
    }
    int ch[4] = {2 * lane, 2 * lane + 1, 64 + 2 * lane, 65 + 2 * lane};
    float mu = (5.0f / 7.0f) * (float)lane;
    float wreg[8][4], bias[4], acc[4] = {0.f, 0.f, 0.f, 0.f};
    #pragma unroll
    for (int c = 0; c < 4; c++) {
        bias[c] = bb_i[ch[c]];
        #pragma unroll
        for (int k = 0; k < 8; k++) wreg[k][c] = Wb_i[k * 128 + ch[c]];
    }
    int s = ptr[w], e = ptr[w + 1];
    int p = s;
    for (; p + 2 <= e; p += 2) {
        int2 e0 = eidx[p];
        int2 e1 = eidx[p + 1];
        float d0 = __int_as_float(e0.y);
        float d1 = __int_as_float(e1.y);
        const __half2* x0 = (const __half2*)(xsrc + (size_t)e0.x * 128);
        const __half2* x1 = (const __half2*)(xsrc + (size_t)e1.x * 128);
        float2 xa0 = __half22float2(x0[lane]);
        float2 xb0 = __half22float2(x0[32 + lane]);
        float2 xa1 = __half22float2(x1[lane]);
        float2 xb1 = __half22float2(x1[32 + lane]);
        float xv0[4] = {xa0.x, xa0.y, xb0.x, xb0.y};
        float xv1[4] = {xa1.x, xa1.y, xb1.x, xb1.y};
        float tt0 = (d0 - mu) * 1.6f, tt1 = (d1 - mu) * 1.6f;
        float rv0 = __expf(-tt0 * tt0), rv1 = __expf(-tt1 * tt1);
        float r0[8], r1[8];
        #pragma unroll
        for (int k = 0; k < 8; k++) {
            r0[k] = __shfl_sync(0xffffffffu, rv0, k);
            r1[k] = __shfl_sync(0xffffffffu, rv1, k);
        }
        #pragma unroll
        for (int c = 0; c < 4; c++) {
            float t0 = bias[c], t1 = bias[c];
            #pragma unroll
            for (int k = 0; k < 8; k++) {
                t0 = fmaf(r0[k], wreg[k][c], t0);
                t1 = fmaf(r1[k], wreg[k][c], t1);
            }
            float sg0 = 1.f / (1.f + __expf(-t0));
            float sg1 = 1.f / (1.f + __expf(-t1));
            acc[c] += (t0 * sg0) * xv0[c] + (t1 * sg1) * xv1[c];
        }
    }
    if (p < e) {
        int2 e0 = eidx[p];
        float d0 = __int_as_float(e0.y);
        const __half2* x0 = (const __half2*)(xsrc + (size_t)e0.x * 128);
        float2 xa0 = __half22float2(x0[lane]);
        float2 xb0 = __half22float2(x0[32 + lane]);
        float xv0[4] = {xa0.x, xa0.y, xb0.x, xb0.y};
        float tt0 = (d0 - mu) * 1.6f;
        float rv0 = __expf(-tt0 * tt0);
        float r0[8];
        #pragma unroll
        for (int k = 0; k < 8; k++) r0[k] = __shfl_sync(0xffffffffu, rv0, k);
        #pragma unroll
        for (int c = 0; c < 4; c++) {
            float t0 = bias[c];
            #pragma unroll
            for (int k = 0; k < 8; k++) t0 = fmaf(r0[k], wreg[k][c], t0);
            float sg0 = 1.f / (1.f + __expf(-t0));
            acc[c] += (t0 * sg0) * xv0[c];
        }
    }
    float inv = 1.f / (float)((e - s) > 1 ? (e - s) : 1);
    __half2* po = (__half2*)(pre + (size_t)w * 128);
    po[lane]      = __floats2half2_rn(acc[0] * inv, acc[1] * inv);
    po[32 + lane] = __floats2half2_rn(acc[2] * inv, acc[3] * inv);
}

// ---------------- fp16 mma fused conv GEMM (both sides, one launch) -----------
// side p: blocks [0, nbp); side l: blocks [nbp, nbp+nbl)
__global__ __launch_bounds__(256, 2) void k_mmac16(
    const __half* __restrict__ A0p, const float* __restrict__ W0p,
    const __half* __restrict__ A1p, const float* __restrict__ W1p,
    const float* __restrict__ biasp, __half* __restrict__ Cp, float* __restrict__ sump,
    const __half* __restrict__ A0l, const float* __restrict__ W0l,
    const __half* __restrict__ A1l, const float* __restrict__ W1l,
    const float* __restrict__ biasl, __half* __restrict__ Cl, float* __restrict__ suml,
    int nbp, int first)
{
    __shared__ unsigned AsH[2 * 8 * 136];
    __shared__ unsigned WsH[2 * 8 * 136];
    int tid = threadIdx.x;
    int by = blockIdx.y;
    const __half *A0, *A1; const float *W0, *W1, *bias;
    __half* C; float* sum; int M, m0;
    if (by < nbp) {
        A0 = A0p; A1 = A1p; W0 = W0p; W1 = W1p; bias = biasp;
        C = Cp; sum = sump; M = NPV; m0 = by * 128;
    } else {
        A0 = A0l; A1 = A1l; W0 = W0l; W1 = W1l; bias = biasl;
        C = Cl; sum = suml; M = NLV; m0 = (by - nbp) * 128;
    }

    int warp = tid >> 5, lane = tid & 31;
    int g = lane >> 2, t = lane & 3;
    int warp_m = warp >> 1, warp_n = warp & 1;

    int le  = tid >> 1;
    int lk8 = (tid & 1) * 8;
    int kp0 = (tid & 1) * 4;
    int arow = m0 + le;
    int wkp = tid >> 5;
    int wc4 = (tid & 31) * 4;

    float4 facc[2][8];
    #pragma unroll
    for (int mt = 0; mt < 2; mt++)
        #pragma unroll
        for (int nt = 0; nt < 8; nt++) facc[mt][nt] = make_float4(0.f, 0.f, 0.f, 0.f);

    uint4 ua = make_uint4(0, 0, 0, 0);
    float4 pw0, pw1;
    {
        if (arow < M) ua = *(const uint4*)(A0 + (size_t)arow * 128 + lk8);
        const float* pw = W0 + (size_t)(2 * wkp) * 128 + wc4;
        pw0 = *(const float4*)pw; pw1 = *(const float4*)(pw + 128);
    }

    for (int kt = 0; kt < 16; kt++) {
        int buf = (kt & 1) * 1088;
        AsH[buf + (kp0 + 0) * 136 + le] = ua.x;
        AsH[buf + (kp0 + 1) * 136 + le] = ua.y;
        AsH[buf + (kp0 + 2) * 136 + le] = ua.z;
        AsH[buf + (kp0 + 3) * 136 + le] = ua.w;
        WsH[buf + wkp * 136 + wc4 + 0] = packh2(pw0.x, pw1.x);
        WsH[buf + wkp * 136 + wc4 + 1] = packh2(pw0.y, pw1.y);
        WsH[buf + wkp * 136 + wc4 + 2] = packh2(pw0.z, pw1.z);
        WsH[buf + wkp * 136 + wc4 + 3] = packh2(pw0.w, pw1.w);
        if (kt + 1 < 16) {
            int kn = kt + 1;
            const __half* Ab = (kn < 8) ? A0 : A1;
            const float* Wb_ = (kn < 8) ? W0 : W1;
            int kl = (kn & 7) * 16;
            ua = make_uint4(0, 0, 0, 0);
            if (arow < M) ua = *(const uint4*)(Ab + (size_t)arow * 128 + kl + lk8);
            const float* pw = Wb_ + (size_t)(kl + 2 * wkp) * 128 + wc4;
            pw0 = *(const float4*)pw; pw1 = *(const float4*)(pw + 128);
        }
        __syncthreads();
        unsigned af[2][4];
        #pragma unroll
        for (int mt = 0; mt < 2; mt++) {
            int rowb = warp_m * 32 + mt * 16;
            af[mt][0] = AsH[buf + t * 136 + rowb + g];
            af[mt][1] = AsH[buf + t * 136 + rowb + g + 8];
            af[mt][2] = AsH[buf + (t + 4) * 136 + rowb + g];
            af[mt][3] = AsH[buf + (t + 4) * 136 + rowb + g + 8];
        }
        #pragma unroll
        for (int nt = 0; nt < 8; nt++) {
            int colb = warp_n * 64 + nt * 8;
            unsigned bf0 = WsH[buf + t * 136 + colb + g];
            unsigned bf1 = WsH[buf + (t + 4) * 136 + colb + g];
            mma_f16(facc[0][nt], af[0][0], af[0][1], af[0][2], af[0][3], bf0, bf1);
            mma_f16(facc[1][nt], af[1][0], af[1][1], af[1][2], af[1][3], bf0, bf1);
        }
    }
    #pragma unroll
    for (int mt = 0; mt < 2; mt++) {
        int rowb = m0 + warp_m * 32 + mt * 16;
        #pragma unroll
        for (int nt = 0; nt < 8; nt++) {
            int col = warp_n * 64 + nt * 8 + 2 * t;
            float ba = bias[col], bb_ = bias[col + 1];
            int r0 = rowb + g, r1 = rowb + g + 8;
            float vx = facc[mt][nt].x + ba, vy = facc[mt][nt].y + bb_;
            float vz = facc[mt][nt].z + ba, vw = facc[mt][nt].w + bb_;
            vx = (vx >= 0.f) ? vx : 0.01f * vx;
            vy = (vy >= 0.f) ? vy : 0.01f * vy;
            vz = (vz >= 0.f) ? vz : 0.01f * vz;
            vw = (vw >= 0.f) ? vw : 0.01f * vw;
            if (r0 < M) {
                *(__half2*)(C + (size_t)r0 * 128 + col) = __floats2half2_rn(vx, vy);
                float2 s;
                if (first) { s.x = vx; s.y = vy; }
                else {
                    s = *(float2*)(sum + (size_t)r0 * 128 + col);
                    s.x += vx; s.y += vy;
                }
                *(float2*)(sum + (size_t)r0 * 128 + col) = s;
            }
            if (r1 < M) {
                *(__half2*)(C + (size_t)r1 * 128 + col) = __floats2half2_rn(vz, vw);
                float2 s;
                if (first) { s.x = vz; s.y = vw; }
                else {
                    s = *(float2*)(sum + (size_t)r1 * 128 + col);
                    s.x += vz; s.y += vw;
                }
                *(float2*)(sum + (size_t)r1 * 128 + col) = s;
            }
        }
    }
}

// ---------------- fp16 mma factor GEMM (both sides, one launch) ---------------
// side l: blocks y in [0, nbl); side p: [nbl, nbl+nbp). N = 512.
__global__ __launch_bounds__(256, 2) void k_mma16(
    const float* __restrict__ Alin, const float* __restrict__ Wl,
    const float* __restrict__ bl, __half* __restrict__ Cl,
    const float* __restrict__ Apin, const float* __restrict__ Wp,
    __half* __restrict__ Cp, int nbl)
{
    const int N = 512;
    __shared__ unsigned AsH[2 * 8 * 136];
    __shared__ unsigned WsH[2 * 8 * 136];
    int tid = threadIdx.x;
    int by = blockIdx.y;
    const float *A, *W, *bias; __half* C; int M, m0;
    if (by < nbl) { A = Alin; W = Wl; bias = bl; C = Cl; M = NLV; m0 = by * 128; }
    else          { A = Apin; W = Wp; bias = nullptr; C = Cp; M = NPV; m0 = (by - nbl) * 128; }
    int n0 = blockIdx.x * 128;

    int warp = tid >> 5, lane = tid & 31;
    int g = lane >> 2, t = lane & 3;
    int warp_m = warp >> 1, warp_n = warp & 1;

    int le  = tid >> 1;
    int lk8 = (tid & 1) * 8;
    int kp0 = (tid & 1) * 4;
    int arow = m0 + le;
    int wkp = tid >> 5;
    int wc4 = (tid & 31) * 4;

    float4 facc[2][8];
    #pragma unroll
    for (int mt = 0; mt < 2; mt++)
        #pragma unroll
        for (int nt = 0; nt < 8; nt++) facc[mt][nt] = make_float4(0.f, 0.f, 0.f, 0.f);

    float4 pa0, pa1, pw0, pw1;
    {
        pa0 = make_float4(0.f,0.f,0.f,0.f); pa1 = pa0;
        if (arow < M) {
            const float* p = A + (size_t)arow * 128 + lk8;
            pa0 = *(const float4*)p; pa1 = *(const float4*)(p + 4);
        }
        const float* pw = W + (size_t)(2 * wkp) * N + n0 + wc4;
        pw0 = *(const float4*)pw; pw1 = *(const float4*)(pw + N);
    }

    for (int kt = 0; kt < 8; kt++) {
        int buf = (kt & 1) * 1088;
        int k = kt * 16;
        AsH[buf + (kp0 + 0) * 136 + le] = packh2(pa0.x, pa0.y);
        AsH[buf + (kp0 + 1) * 136 + le] = packh2(pa0.z, pa0.w);
        AsH[buf + (kp0 + 2) * 136 + le] = packh2(pa1.x, pa1.y);
        AsH[buf + (kp0 + 3) * 136 + le] = packh2(pa1.z, pa1.w);
        WsH[buf + wkp * 136 + wc4 + 0] = packh2(pw0.x, pw1.x);
        WsH[buf + wkp * 136 + wc4 + 1] = packh2(pw0.y, pw1.y);
        WsH[buf + wkp * 136 + wc4 + 2] = packh2(pw0.z, pw1.z);
        WsH[buf + wkp * 136 + wc4 + 3] = packh2(pw0.w, pw1.w);
        if (kt + 1 < 8) {
            int kn = k + 16;
            pa0 = make_float4(0.f,0.f,0.f,0.f); pa1 = pa0;
            if (arow < M) {
                const float* p = A + (size_t)arow * 128 + kn + lk8;
                pa0 = *(const float4*)p; pa1 = *(const float4*)(p + 4);
            }
            const float* pw = W + (size_t)(kn + 2 * wkp) * N + n0 + wc4;
            pw0 = *(const float4*)pw; pw1 = *(const float4*)(pw + N);
        }
        __syncthreads();
        unsigned af[2][4];
        #pragma unroll
        for (int mt = 0; mt < 2; mt++) {
            int rowb = warp_m * 32 + mt * 16;
            af[mt][0] = AsH[buf + t * 136 + rowb + g];
            af[mt][1] = AsH[buf + t * 136 + rowb + g + 8];
            af[mt][2] = AsH[buf + (t + 4) * 136 + rowb + g];
            af[mt][3] = AsH[buf + (t + 4) * 136 + rowb + g + 8];
        }
        #pragma unroll
        for (int nt = 0; nt < 8; nt++) {
            int colb = warp_n * 64 + nt * 8;
            unsigned bf0 = WsH[buf + t * 136 + colb + g];
            unsigned bf1 = WsH[buf + (t + 4) * 136 + colb + g];
            mma_f16(facc[0][nt], af[0][0], af[0][1], af[0][2], af[0][3], bf0, bf1);
            mma_f16(facc[1][nt], af[1][0], af[1][1], af[1][2], af[1][3], bf0, bf1);
        }
    }
    #pragma unroll
    for (int mt = 0; mt < 2; mt++) {
        int rowb = m0 + warp_m * 32 + mt * 16;
        #pragma unroll
        for (int nt = 0; nt < 8; nt++) {
            int col = n0 + warp_n * 64 + nt * 8 + 2 * t;
            float ba = 0.f, bb_ = 0.f;
            if (bias) { ba = bias[col]; bb_ = bias[col + 1]; }
            int r0 = rowb + g, r1 = rowb + g + 8;
            if (r0 < M)
                *(__half2*)(C + (size_t)r0 * N + col) =
                    __floats2half2_rn(facc[mt][nt].x + ba, facc[mt][nt].y + bb_);
            if (r1 < M)
                *(__half2*)(C + (size_t)r1 * N + col) =
                    __floats2half2_rn(facc[mt][nt].z + ba, facc[mt][nt].w + bb_);
        }
    }
}

// ---------------- cvec ----------------
__global__ void k_cvec(const float* __restrict__ W_el, const float* __restrict__ W1) {
    int j = blockIdx.x * 256 + threadIdx.x;
    if (j < 512) {
        float s = 0.f;
        #pragma unroll
        for (int k = 0; k < 8; k++) s = fmaf(W_el[k], W1[(size_t)(256 + k) * 512 + j], s);
        g_cvec[j] = s;
    }
}

__global__ void k_init_out() {
    int i = blockIdx.x * 256 + threadIdx.x;
    if (i < NGV * 128) { g_out_w[i] = 0.f; g_out_max[i] = -INFINITY; }
}

// ---------------- fused edge MLP + per-graph reduction: 128-edge tiles ------------
#define EDGE_SMEM_FLOATS 22272
__global__ __launch_bounds__(256, 2) void k_edge(
    const __half* __restrict__ Al, const __half* __restrict__ Bp,
    const float* __restrict__ W2, const float* __restrict__ b2,
    const float* __restrict__ Wm, const float* __restrict__ bm)
{
    extern __shared__ float dynsm[];
    unsigned* AsH = (unsigned*)dynsm;
    unsigned* WsH = (unsigned*)(dynsm + 2176);
    float* smm  = dynsm + 4352;
    float* cs   = dynsm + 21248;
    float* se_d = dynsm + 21760;
    int*   se_a = (int*)(dynsm + 21888);
    int*   se_b = (int*)(dynsm + 22016);
    int*   se_g = (int*)(dynsm + 22144);

    int tid = threadIdx.x;
    int t0 = blockIdx.x * 128;
    if (tid < 128) {
        int slot = t0 + tid;
        if (slot < EV) {
            int4 r = g_src_rec[slot];
            se_a[tid] = r.x; se_b[tid] = r.y;
            se_d[tid] = __int_as_float(r.z);
            se_g[tid] = r.w;
        } else { se_a[tid] = 0; se_b[tid] = 0; se_d[tid] = 0.f; se_g[tid] = -1; }
    }
    for (int i = tid; i < 512; i += 256) cs[i] = g_cvec[i];
    __syncthreads();

    int warp = tid >> 5, lane = tid & 31;
    int g = lane >> 2, t = lane & 3;
    int warp_m = warp >> 1, warp_n = warp & 1;

    int le  = tid >> 1;
    int lk8 = (tid & 1) * 8;
    int kp0 = (tid & 1) * 4;
    const __half* arow = Al + (size_t)se_a[le] * 512;
    const __half* brow = Bp + (size_t)se_b[le] * 512;
    float dv = se_d[le];
    int wkp = tid >> 5;
    int wc4 = (tid & 31) * 4;

    // ---- GEMM 1 (fp16 mma): m = relu(A[src]+B[dst]+d*cvec) @ W2 ----
    float4 facc[2][8];
    #pragma unroll
    for (int mt = 0; mt < 2; mt++)
        #pragma unroll
        for (int nt = 0; nt < 8; nt++) facc[mt][nt] = make_float4(0.f, 0.f, 0.f, 0.f);

    uint4 pa, pb;
    float4 pw0, pw1;
    {
        pa = *(const uint4*)(arow + lk8);
        pb = *(const uint4*)(brow + lk8);
        const float* pw = W2 + (size_t)(2 * wkp) * 128 + wc4;
        pw0 = *(const float4*)pw; pw1 = *(const float4*)(pw + 128);
    }

    for (int kt = 0; kt < 32; kt++) {
        int buf = (kt & 1) * 1088;
        int k = kt * 16;
        float4 c0 = *(const float4*)(cs + k + lk8), c1 = *(const float4*)(cs + k + lk8 + 4);
        const __half2* a2 = (const __half2*)&pa;
        const __half2* b2v = (const __half2*)&pb;
        float2 fa0 = __half22float2(a2[0]), fb0 = __half22float2(b2v[0]);
        float2 fa1 = __half22float2(a2[1]), fb1 = __half22float2(b2v[1]);
        float2 fa2 = __half22float2(a2[2]), fb2 = __half22float2(b2v[2]);
        float2 fa3 = __half22float2(a2[3]), fb3 = __half22float2(b2v[3]);
        float h0 = fmaxf(fa0.x + fb0.x + dv * c0.x, 0.f);
        float h1 = fmaxf(fa0.y + fb0.y + dv * c0.y, 0.f);
        float h2 = fmaxf(fa1.x + fb1.x + dv * c0.z, 0.f);
        float h3 = fmaxf(fa1.y + fb1.y + dv * c0.w, 0.f);
        float h4 = fmaxf(fa2.x + fb2.x + dv * c1.x, 0.f);
        float h5 = fmaxf(fa2.y + fb2.y + dv * c1.y, 0.f);
        float h6 = fmaxf(fa3.x + fb3.x + dv * c1.z, 0.f);
        float h7 = fmaxf(fa3.y + fb3.y + dv * c1.w, 0.f);
        AsH[buf + (kp0 + 0) * 136 + le] = packh2(h0, h1);
        AsH[buf + (kp0 + 1) * 136 + le] = packh2(h2, h3);
        AsH[buf + (kp0 + 2) * 136 + le] = packh2(h4, h5);
        AsH[buf + (kp0 + 3) * 136 + le] = packh2(h6, h7);
        WsH[buf + wkp * 136 + wc4 + 0] = packh2(pw0.x, pw1.x);
        WsH[buf + wkp * 136 + wc4 + 1] = packh2(pw0.y, pw1.y);
        WsH[buf + wkp * 136 + wc4 + 2] = packh2(pw0.z, pw1.z);
        WsH[buf + wkp * 136 + wc4 + 3] = packh2(pw0.w, pw1.w);
        if (kt + 1 < 32) {
            int kn = k + 16;
            pa = *(const uint4*)(arow + kn + lk8);
            pb = *(const uint4*)(brow + kn + lk8);
            const float* pw = W2 + (size_t)(kn + 2 * wkp) * 128 + wc4;
            pw0 = *(const float4*)pw; pw1 = *(const float4*)(pw + 128);
        }
        __syncthreads();
        unsigned af[2][4];
        #pragma unroll
        for (int mt = 0; mt < 2; mt++) {
            int rowb = warp_m * 32 + mt * 16;
            af[mt][0] = AsH[buf + t * 136 + rowb + g];
            af[mt][1] = AsH[buf + t * 136 + rowb + g + 8];
            af[mt][2] = AsH[buf + (t + 4) * 136 + rowb + g];
            af[mt][3] = AsH[buf + (t + 4) * 136 + rowb + g + 8];
        }
        #pragma unroll
        for (int nt = 0; nt < 8; nt++) {
            int colb = warp_n * 64 + nt * 8;
            unsigned bf0 = WsH[buf + t * 136 + colb + g];
            unsigned bf1 = WsH[buf + (t + 4) * 136 + colb + g];
            mma_f16(facc[0][nt], af[0][0], af[0][1], af[0][2], af[0][3], bf0, bf1);
            mma_f16(facc[1][nt], af[1][0], af[1][1], af[1][2], af[1][3], bf0, bf1);
        }
    }
    __syncthreads();

    // m = facc + b2 -> smm (fragment-layout stores, fp32)
    #pragma unroll
    for (int mt = 0; mt < 2; mt++) {
        int rowb = warp_m * 32 + mt * 16;
        #pragma unroll
        for (int nt = 0; nt < 8; nt++) {
            int cc = warp_n * 64 + nt * 8 + 2 * t;
            float ba = b2[cc], bb_ = b2[cc + 1];
            *(float2*)(smm + (rowb + g) * 132 + cc) =
                make_float2(facc[mt][nt].x + ba, facc[mt][nt].y + bb_);
            *(float2*)(smm + (rowb + g + 8) * 132 + cc) =
                make_float2(facc[mt][nt].z + ba, facc[mt][nt].w + bb_);
        }
    }
    __syncthreads();

    // ---- GEMM 2 (fp16 mma): u = m @ Wm ; w = tanh(u + bm) ----
    float4 facc2[2][8];
    #pragma unroll
    for (int mt = 0; mt < 2; mt++)
        #pragma unroll
        for (int nt = 0; nt < 8; nt++) facc2[mt][nt] = make_float4(0.f, 0.f, 0.f, 0.f);

    {
        const float* pw = Wm + (size_t)(2 * wkp) * 128 + wc4;
        pw0 = *(const float4*)pw; pw1 = *(const float4*)(pw + 128);
    }
    for (int kt = 0; kt < 8; kt++) {
        int buf = (kt & 1) * 1088;
        int k = kt * 16;
        WsH[buf + wkp * 136 + wc4 + 0] = packh2(pw0.x, pw1.x);
        WsH[buf + wkp * 136 + wc4 + 1] = packh2(pw0.y, pw1.y);
        WsH[buf + wkp * 136 + wc4 + 2] = packh2(pw0.z, pw1.z);
        WsH[buf + wkp * 136 + wc4 + 3] = packh2(pw0.w, pw1.w);
        if (kt + 1 < 8) {
            const float* pw = Wm + (size_t)(k + 16 + 2 * wkp) * 128 + wc4;
            pw0 = *(const float4*)pw; pw1 = *(const float4*)(pw + 128);
        }
        __syncthreads();
        unsigned af[2][4];
        #pragma unroll
        for (int mt = 0; mt < 2; mt++) {
            int rowb = warp_m * 32 + mt * 16;
            const float* r0p = smm + (rowb + g) * 132 + k;
            const float* r1p = smm + (rowb + g + 8) * 132 + k;
            af[mt][0] = packh2(r0p[2 * t], r0p[2 * t + 1]);
            af[mt][1] = packh2(r1p[2 * t], r1p[2 * t + 1]);
            af[mt][2] = packh2(r0p[2 * t + 8], r0p[2 * t + 9]);
            af[mt][3] = packh2(r1p[2 * t + 8], r1p[2 * t + 9]);
        }
        #pragma unroll
        for (int nt = 0; nt < 8; nt++) {
            int colb = warp_n * 64 + nt * 8;
            unsigned bf0 = WsH[buf + t * 136 + colb + g];
            unsigned bf1 = WsH[buf + (t + 4) * 136 + colb + g];
            mma_f16(facc2[0][nt], af[0][0], af[0][1], af[0][2], af[0][3], bf0, bf1);
            mma_f16(facc2[1][nt], af[1][0], af[1][1], af[1][2], af[1][3], bf0, bf1);
        }
    }

    // ---- per-graph reduction (fragment layout) ----
    {
        int row_block = warp_m * 32;
        bool uniform = (se_g[row_block] == se_g[row_block + 31]) && (se_g[row_block] >= 0);
        if (uniform) {
            int gg = se_g[row_block];
            #pragma unroll
            for (int nt = 0; nt < 8; nt++) {
                int cc = warp_n * 64 + nt * 8 + 2 * t;
                float b0 = bm[cc], b1 = bm[cc + 1];
                float ps0 = 0.f, ps1 = 0.f, mx0 = -INFINITY, mx1 = -INFINITY;
                #pragma unroll
                for (int mt = 0; mt < 2; mt++) {
                    int r0 = warp_m * 32 + mt * 16 + g, r1 = r0 + 8;
                    float m00 = smm[r0 * 132 + cc], m01 = smm[r0 * 132 + cc + 1];
                    float m10 = smm[r1 * 132 + cc], m11 = smm[r1 * 132 + cc + 1];
                    ps0 += fast_tanh(facc2[mt][nt].x + b0) * m00
                         + fast_tanh(facc2[mt][nt].z + b0) * m10;
                    ps1 += fast_tanh(facc2[mt][nt].y + b1) * m01
                         + fast_tanh(facc2[mt][nt].w + b1) * m11;
                    mx0 = fmaxf(mx0, fmaxf(m00, m10));
                    mx1 = fmaxf(mx1, fmaxf(m01, m11));
                }
                #pragma unroll
                for (int off = 4; off < 32; off <<= 1) {
                    ps0 += __shfl_xor_sync(0xffffffffu, ps0, off);
                    ps1 += __shfl_xor_sync(0xffffffffu, ps1, off);
                    mx0 = fmaxf(mx0, __shfl_xor_sync(0xffffffffu, mx0, off));
                    mx1 = fmaxf(mx1, __shfl_xor_sync(0xffffffffu, mx1, off));
                }
                if (g == 0) {
                    atomicAdd(&g_out_w[gg * 128 + cc], ps0);
                    atomicAdd(&g_out_w[gg * 128 + cc + 1], ps1);
                    atomicMaxFloat(&g_out_max[gg * 128 + cc], mx0);
                    atomicMaxFloat(&g_out_max[gg * 128 + cc + 1], mx1);
                }
            }
        } else {
            #pragma unroll
            for (int nt = 0; nt < 8; nt++) {
                int cc = warp_n * 64 + nt * 8 + 2 * t;
                float b0 = bm[cc], b1 = bm[cc + 1];
                #pragma unroll
                for (int mt = 0; mt < 2; mt++) {
                    int r0 = warp_m * 32 + mt * 16 + g, r1 = r0 + 8;
                    int g0 = se_g[r0], g1 = se_g[r1];
                    if (g0 >= 0) {
                        float m00 = smm[r0 * 132 + cc], m01 = smm[r0 * 132 + cc + 1];
                        atomicAdd(&g_out_w[g0 * 128 + cc],
                                  fast_tanh(facc2[mt][nt].x + b0) * m00);
                        atomicAdd(&g_out_w[g0 * 128 + cc + 1],
                                  fast_tanh(facc2[mt][nt].y + b1) * m01);
                        atomicMaxFloat(&g_out_max[g0 * 128 + cc], m00);
                        atomicMaxFloat(&g_out_max[g0 * 128 + cc + 1], m01);
                    }
                    if (g1 >= 0) {
                        float m10 = smm[r1 * 132 + cc], m11 = smm[r1 * 132 + cc + 1];
                        atomicAdd(&g_out_w[g1 * 128 + cc],
                                  fast_tanh(facc2[mt][nt].z + b0) * m10);
                        atomicAdd(&g_out_w[g1 * 128 + cc + 1],
                                  fast_tanh(facc2[mt][nt].w + b1) * m11);
                        atomicMaxFloat(&g_out_max[g1 * 128 + cc], m10);
                        atomicMaxFloat(&g_out_max[g1 * 128 + cc + 1], m11);
                    }
                }
            }
        }
    }
}

__global__ void k_final(float* __restrict__ out) {
    int i = blockIdx.x * 256 + threadIdx.x;
    if (i < NGV * 256) {
        int g = i >> 8, j = i & 255;
        float v;
        if (j < 128) v = g_out_w[g * 128 + j];
        else {
            v = g_out_max[g * 128 + j - 128];
            if (!isfinite(v)) v = 0.f;
        }
        out[i] = v;
    }
}

// ---------------- host orchestration ----------------
#define SYM(p, s) do { void* _t = nullptr; cudaGetSymbolAddress(&_t, s); p = (decltype(p))_t; } while (0)

extern "C" void kernel_launch(void* const* d_in, const int* in_sizes, int n_in,
                              void* d_out, int out_size) {
    const float* x_l    = (const float*)d_in[0];
    const float* x_p    = (const float*)d_in[1];
    const float* ea     = (const float*)d_in[2];
    const int*   esrc   = (const int*)  d_in[3];
    const int*   edst   = (const int*)  d_in[4];
    const int*   lbatch = (const int*)  d_in[5];
    const float* W_node = (const float*)d_in[6];
    const float* W_el   = (const float*)d_in[7];
    const float* Wb     = (const float*)d_in[8];
    const float* bb     = (const float*)d_in[9];
    const float* Wn     = (const float*)d_in[10];
    const float* Ws_    = (const float*)d_in[11];
    const float* bconv  = (const float*)d_in[12];
    const float* W1     = (const float*)d_in[13];
    const float* b1     = (const float*)d_in[14];
    const float* W2     = (const float*)d_in[15];
    const float* b2     = (const float*)d_in[16];
    const float* Wm     = (const float*)d_in[17];
    const float* bm     = (const float*)d_in[18];

    __half *xl, *xl2, *prel, *xp, *xp2, *prep, *Ah, *Bh;
    float *xlsum, *xpsum;
    int *dcnt, *dptr, *scnt, *sptr, *stmp, *bsum;
    SYM(xl, g_xl); SYM(xl2, g_xl2); SYM(xlsum, g_xlsum); SYM(prel, g_prel);
    SYM(xp, g_xp); SYM(xp2, g_xp2); SYM(xpsum, g_xpsum); SYM(prep, g_prep);
    SYM(Ah, g_Ah); SYM(Bh, g_Bh);
    SYM(dcnt, g_dst_cnt); SYM(dptr, g_dst_ptr);
    SYM(scnt, g_src_cnt); SYM(sptr, g_src_ptr);
    SYM(stmp, g_scan_tmp); SYM(bsum, g_bsum);

    cudaFuncSetAttribute(k_edge, cudaFuncAttributeMaxDynamicSharedMemorySize,
                         EDGE_SMEM_FLOATS * (int)sizeof(float));

    // node embedding (fp16 out)
    k_embed<<<(NLV + 3) / 4, 128>>>(x_l, xl, W_node, NLV);
    k_embed<<<(NPV + 3) / 4, 128>>>(x_p, xp, W_node, NPV);

    // cvec
    k_cvec<<<2, 256>>>(W_el, W1);

    // CSR (dst and src)
    cudaMemsetAsync(dcnt, 0, NPV * sizeof(int));
    cudaMemsetAsync(scnt, 0, NLV * sizeof(int));
    k_hist<<<(EV + 255) / 256, 256>>>(esrc, edst);
    int nbp1 = (NPV + 1023) / 1024, nbl1 = (NLV + 1023) / 1024;
    k_scan1<<<nbp1, 1024>>>(dcnt, stmp, bsum, NPV);
    k_scan2<<<1, 512>>>(bsum, nbp1);
    k_scan3<<<nbp1, 1024>>>(stmp, bsum, dptr, NPV);
    k_scan1<<<nbl1, 1024>>>(scnt, stmp, bsum, NLV);
    k_scan2<<<1, 512>>>(bsum, nbl1);
    k_scan3<<<nbl1, 1024>>>(stmp, bsum, sptr, NLV);
    cudaMemsetAsync(dcnt, 0, NPV * sizeof(int));
    cudaMemsetAsync(scnt, 0, NLV * sizeof(int));
    k_fill<<<(EV + 255) / 256, 256>>>(esrc, edst, ea, lbatch);

    // 3 hetero layers (merged conv launches; layer 0 writes sums)
    int nbp = (NPV + 127) / 128, nbl = (NLV + 127) / 128;
    __half *cxl = xl, *cxp = xp, *nxl = xl2, *nxp = xp2;
    for (int l = 0; l < 3; l++) {
        int ilp = 2 * l, ipl = 2 * l + 1;
        k_agg2<<<((NPV + NLV) * 32 + 255) / 256, 256>>>(cxl, cxp,
                Wb + ilp * 1024, bb + ilp * 128,
                Wb + ipl * 1024, bb + ipl * 128, prep, prel);
        k_mmac16<<<dim3(1, nbp + nbl), 256>>>(
                cxp, Ws_ + (size_t)ilp * 16384, prep, Wn + (size_t)ilp * 16384,
                bconv + ilp * 128, nxp, xpsum,
                cxl, Ws_ + (size_t)ipl * 16384, prel, Wn + (size_t)ipl * 16384,
                bconv + ipl * 128, nxl, xlsum,
                nbp, (l == 0) ? 1 : 0);
        __half* t;
        t = cxl; cxl = nxl; nxl = t;
        t = cxp; cxp = nxp; nxp = t;
    }

    // edge readout factorization (both sides, one launch)
    k_mma16<<<dim3(4, nbl + nbp), 256>>>(xlsum, W1, b1, Ah,
                                         xpsum, W1 + (size_t)128 * 512, Bh, nbl);

    k_init_out<<<(NGV * 128 + 255) / 256, 256>>>();
    k_edge<<<(EV + 127) / 128, 256, EDGE_SMEM_FLOATS * (int)sizeof(float)>>>(
            Ah, Bh, W2, b2, Wm, bm);
    k_final<<<(NGV * 256 + 255) / 256, 256>>>((float*)d_out);
}